// round 14
// baseline (speedup 1.0000x reference)
#include <cuda_runtime.h>
#include <cuda_fp16.h>
#include <stdint.h>
#include <math.h>

#define L_    512
#define N_    512
#define DIN_  128
#define H_    256
#define DOUT_ 64
#define G3    768
#define LN    262144

typedef unsigned long long ull;

// ---- scratch ----
__device__ __half g_gx16[(size_t)LN * G3];      // input projections fp16
__device__ __half g_h16[(size_t)LN * H_];       // hidden states fp16 (heads input)
__device__ __half g_whh16[(size_t)G3 * H_];     // W_hh fp16 (768,256)
__device__ __half g_wih16[(size_t)G3 * DIN_];   // W_ih fp16 (768,128)
__device__ __half g_whd16[(size_t)128 * H_];    // [W_mu;W_lv] fp16 (128,256) n-major

// ---------------- helpers ----------------
__device__ __forceinline__ uint32_t smem_u32(const void* p) {
    uint32_t a;
    asm("{ .reg .u64 t; cvta.to.shared.u64 t, %1; cvt.u32.u64 %0, t; }" : "=r"(a) : "l"(p));
    return a;
}
__device__ __forceinline__ uint32_t mapa_u32(uint32_t addr, uint32_t rank) {
    uint32_t r;
    asm volatile("mapa.shared::cluster.u32 %0, %1, %2;" : "=r"(r) : "r"(addr), "r"(rank));
    return r;
}
__device__ __forceinline__ void st_cluster_u32(uint32_t addr, unsigned v) {
    asm volatile("st.shared::cluster.u32 [%0], %1;" :: "r"(addr), "r"(v) : "memory");
}
__device__ __forceinline__ uint32_t my_rank() {
    uint32_t r;
    asm("mov.u32 %0, %%cluster_ctarank;" : "=r"(r));
    return r;
}
#define CLUSTER_BAR() do {                                        \
    asm volatile("barrier.cluster.arrive.aligned;" ::: "memory"); \
    asm volatile("barrier.cluster.wait.aligned;" ::: "memory");   \
} while (0)

// mbarrier: remote release-arrive (cluster scope) on CTA `rank`'s mbar
__device__ __forceinline__ void mbar_arrive_cluster(uint32_t local_addr, uint32_t rank) {
    asm volatile(
        "{\n\t"
        ".reg .b32 ra;\n\t"
        "mapa.shared::cluster.u32 ra, %0, %1;\n\t"
        "mbarrier.arrive.release.cluster.shared::cluster.b64 _, [ra];\n\t"
        "}"
        :: "r"(local_addr), "r"(rank) : "memory");
}
// local acquire-wait (cluster scope) on parity
__device__ __forceinline__ void mbar_wait_parity_cluster(uint32_t addr, uint32_t parity) {
    asm volatile(
        "{\n\t"
        ".reg .pred P;\n\t"
        "WAIT_%=:\n\t"
        "mbarrier.try_wait.parity.acquire.cluster.shared::cta.b64 P, [%0], %1;\n\t"
        "@P bra.uni DONE_%=;\n\t"
        "bra.uni WAIT_%=;\n\t"
        "DONE_%=:\n\t"
        "}"
        :: "r"(addr), "r"(parity) : "memory");
}

__device__ __forceinline__ void hmma16816(float* c, unsigned a0, unsigned a1,
                                          unsigned a2, unsigned a3,
                                          unsigned b0, unsigned b1) {
    asm volatile(
        "mma.sync.aligned.m16n8k16.row.col.f32.f16.f16.f32 "
        "{%0,%1,%2,%3}, {%4,%5,%6,%7}, {%8,%9}, {%0,%1,%2,%3};"
        : "+f"(c[0]), "+f"(c[1]), "+f"(c[2]), "+f"(c[3])
        : "r"(a0), "r"(a1), "r"(a2), "r"(a3), "r"(b0), "r"(b1));
}

// ---------------- weight prep ----------------
__global__ void prep_weights(const float* __restrict__ Whh, const float* __restrict__ Wih,
                             const float* __restrict__ Wmu, const float* __restrict__ Wlv,
                             __half* __restrict__ whh16, __half* __restrict__ wih16,
                             __half* __restrict__ whd16)
{
    int i = blockIdx.x * blockDim.x + threadIdx.x;
    if (i < G3 * H_) {
        whh16[i] = __float2half_rn(Whh[i]);
    } else if (i < G3 * H_ + G3 * DIN_) {
        int j = i - G3 * H_;
        wih16[j] = __float2half_rn(Wih[j]);
    } else if (i < G3 * H_ + G3 * DIN_ + 128 * H_) {
        int j = i - G3 * H_ - G3 * DIN_;
        int d = j / H_;
        whd16[j] = __float2half_rn((d < 64) ? Wmu[j] : Wlv[j - 64 * H_]);
    }
}

// ---------------- gx GEMM via HMMA: fp32 x in (converted in staging), fp16 out ----------------
#define GXH_SMEM ((128 * 136 + 192 * 136) * 2)
__global__ void __launch_bounds__(512, 1)
gemm_gx_hmma(const float*  __restrict__ X,      // (LN,128) fp32
             const __half* __restrict__ W16,    // (768,128) fp16 n-major
             const float*  __restrict__ bias,   // (768)
             __half*       __restrict__ C16)    // (LN,768) fp16
{
    extern __shared__ __half hsm[];
    __half* Xs = hsm;              // [128][136]
    __half* Ws = hsm + 128 * 136;  // [192][136]

    const int tid = threadIdx.x;
    const int m0  = blockIdx.y * 128;
    const int n0  = blockIdx.x * 192;

    // stage x: fp32 -> fp16 in-flight
#pragma unroll
    for (int f = tid; f < 128 * 32; f += 512) {
        int m = f >> 5, c = f & 31;
        float4 v = *(const float4*)&X[((size_t)(m0 + m)) * DIN_ + 4 * c];
        __half2 h0 = __floats2half2_rn(v.x, v.y);
        __half2 h1 = __floats2half2_rn(v.z, v.w);
        *(__half2*)&Xs[m * 136 + 4 * c]     = h0;
        *(__half2*)&Xs[m * 136 + 4 * c + 2] = h1;
    }
#pragma unroll
    for (int f = tid; f < 192 * 16; f += 512) {
        int n = f >> 4, c = f & 15;
        int4 v = *(const int4*)&W16[((size_t)(n0 + n)) * DIN_ + c * 8];
        *(int4*)&Ws[n * 136 + c * 8] = v;
    }
    __syncthreads();

    const int warp = tid >> 5, lane = tid & 31;
    const int wm = warp >> 2, wn = warp & 3;
    const int mb = wm * 32, nb = wn * 48;
    const int g = lane >> 2, tig = lane & 3;

    float acc[2][6][4];
#pragma unroll
    for (int mt = 0; mt < 2; mt++)
#pragma unroll
        for (int nt = 0; nt < 6; nt++)
#pragma unroll
            for (int q = 0; q < 4; q++) acc[mt][nt][q] = 0.0f;

#pragma unroll
    for (int kc = 0; kc < 8; kc++) {
        int k0 = kc * 16;
        unsigned a[2][4];
#pragma unroll
        for (int mt = 0; mt < 2; mt++) {
            int r = mb + mt * 16 + g;
            a[mt][0] = *(const unsigned*)&Xs[r * 136 + k0 + 2 * tig];
            a[mt][1] = *(const unsigned*)&Xs[(r + 8) * 136 + k0 + 2 * tig];
            a[mt][2] = *(const unsigned*)&Xs[r * 136 + k0 + 2 * tig + 8];
            a[mt][3] = *(const unsigned*)&Xs[(r + 8) * 136 + k0 + 2 * tig + 8];
        }
#pragma unroll
        for (int nt = 0; nt < 6; nt++) {
            int n = nb + nt * 8 + g;
            unsigned b0 = *(const unsigned*)&Ws[n * 136 + k0 + 2 * tig];
            unsigned b1 = *(const unsigned*)&Ws[n * 136 + k0 + 2 * tig + 8];
#pragma unroll
            for (int mt = 0; mt < 2; mt++)
                hmma16816(acc[mt][nt], a[mt][0], a[mt][1], a[mt][2], a[mt][3], b0, b1);
        }
    }

#pragma unroll
    for (int nt = 0; nt < 6; nt++) {
        int col = n0 + nb + nt * 8 + 2 * tig;
        float b0 = __ldg(&bias[col]);
        float b1 = __ldg(&bias[col + 1]);
#pragma unroll
        for (int mt = 0; mt < 2; mt++) {
            size_t row = (size_t)m0 + mb + mt * 16 + g;
            __half2 o0 = __floats2half2_rn(acc[mt][nt][0] + b0, acc[mt][nt][1] + b1);
            __half2 o1 = __floats2half2_rn(acc[mt][nt][2] + b0, acc[mt][nt][3] + b1);
            *(__half2*)&C16[row * G3 + col]       = o0;
            *(__half2*)&C16[(row + 8) * G3 + col] = o1;
        }
    }
}

// ---------------- cluster-cooperative HMMA GRU scan, v5 ----------------
// Same work partition as v4 (16 warps, 2-way K-split, gate-owner warps kh=0),
// but the per-step cluster barrier is replaced by an mbarrier protocol:
// owners store h remotely -> __syncthreads -> tid0 release-arrives on all 4
// CTAs' mbars -> all threads acquire-wait local parity. gx is fp16.
__global__ void __launch_bounds__(512, 1) __cluster_dims__(4, 1, 1)
gru_scan_cluster(const __half* __restrict__ gx,      // (L,N,768) fp16
                 const __half* __restrict__ W16,     // (768,256) fp16
                 const float*  __restrict__ b_hh,    // (768)
                 __half*       __restrict__ h16buf,  // (L,N,256) fp16
                 float*        __restrict__ hn_out)  // (N,256) fp32
{
    __shared__ __half h16[2][16 * 264];        // double-buffered fp16 h tile
    __shared__ float  red[8 * 32 * 12];        // K-split partials
    __shared__ __align__(8) ull mbar[1];       // step barrier (count=4)

    const int tid  = threadIdx.x;
    const int wid  = tid >> 5;
    const int kh   = wid >> 3;                 // K-half
    const int ug   = wid & 7;                  // unit group
    const int lane = tid & 31;
    const int g    = lane >> 2, tig = lane & 3;
    const uint32_t rk = my_rank();
    const int c0row = (blockIdx.x >> 2) * 16;
    const uint32_t h16_b  = smem_u32(&h16[0][0]);
    const uint32_t mbar_b = smem_u32(&mbar[0]);

    // zero both h buffers (h0 = 0); init mbar
    for (int i = tid; i < 2 * 16 * 264 / 2; i += 512) ((unsigned*)&h16[0][0])[i] = 0u;
    if (tid == 0)
        asm volatile("mbarrier.init.shared.b64 [%0], 4;" :: "r"(mbar_b) : "memory");

    const int j0 = ug * 8 + 2 * tig;
    const int jg = (int)rk * 64 + j0;

    unsigned bfr[3][8][2];
#pragma unroll
    for (int gate = 0; gate < 3; gate++) {
        int n = gate * 256 + (int)rk * 64 + ug * 8 + g;
        const __half* wp = W16 + (size_t)n * H_ + 2 * tig;
#pragma unroll
        for (int ks = 0; ks < 8; ks++) {
            int kso = kh * 8 + ks;
            bfr[gate][ks][0] = *(const unsigned*)(wp + kso * 16);
            bfr[gate][ks][1] = *(const unsigned*)(wp + kso * 16 + 8);
        }
    }

    const float2 bR = *(const float2*)&b_hh[jg];
    const float2 bZ = *(const float2*)&b_hh[H_ + jg];
    const float2 bN = *(const float2*)&b_hh[2 * H_ + jg];
    float hprev[4] = {0.f, 0.f, 0.f, 0.f};

    __half2 cur[3][2], nxt[3][2];
    if (kh == 0) {
        const __half* p0 = gx + ((size_t)c0row + g) * G3 + jg;
        const __half* p1 = gx + ((size_t)c0row + g + 8) * G3 + jg;
#pragma unroll
        for (int gate = 0; gate < 3; gate++) {
            cur[gate][0] = *(const __half2*)(p0 + gate * H_);
            cur[gate][1] = *(const __half2*)(p1 + gate * H_);
        }
    }

    const int rbase = (ug * 32 + lane) * 12;

    CLUSTER_BAR();   // once: zeroed tiles + mbar init visible cluster-wide

    for (int t = 0; t < L_; t++) {
        const int p = t & 1;
        const __half* hp = &h16[p][0];

        // prefetch gx(t+1) first (drains under MMA + gate)
        if (kh == 0 && t + 1 < L_) {
            const __half* p0 = gx + ((size_t)(t + 1) * N_ + c0row + g) * G3 + jg;
            const __half* p1 = gx + ((size_t)(t + 1) * N_ + c0row + g + 8) * G3 + jg;
#pragma unroll
            for (int gate = 0; gate < 3; gate++) {
                nxt[gate][0] = *(const __half2*)(p0 + gate * H_);
                nxt[gate][1] = *(const __half2*)(p1 + gate * H_);
            }
        }

        // MMA: 3 gates x 8 ksteps (this warp's K-half)
        float cR[4] = {0.f, 0.f, 0.f, 0.f};
        float cZ[4] = {0.f, 0.f, 0.f, 0.f};
        float cN[4] = {0.f, 0.f, 0.f, 0.f};
#pragma unroll
        for (int ks = 0; ks < 8; ks++) {
            int ko = (kh * 8 + ks) * 16 + 2 * tig;
            unsigned a0 = *(const unsigned*)&hp[g * 264 + ko];
            unsigned a1 = *(const unsigned*)&hp[(g + 8) * 264 + ko];
            unsigned a2 = *(const unsigned*)&hp[g * 264 + ko + 8];
            unsigned a3 = *(const unsigned*)&hp[(g + 8) * 264 + ko + 8];
            hmma16816(cR, a0, a1, a2, a3, bfr[0][ks][0], bfr[0][ks][1]);
            hmma16816(cZ, a0, a1, a2, a3, bfr[1][ks][0], bfr[1][ks][1]);
            hmma16816(cN, a0, a1, a2, a3, bfr[2][ks][0], bfr[2][ks][1]);
        }

        if (kh == 1) {
            *(float4*)&red[rbase]     = make_float4(cR[0], cR[1], cR[2], cR[3]);
            *(float4*)&red[rbase + 4] = make_float4(cZ[0], cZ[1], cZ[2], cZ[3]);
            *(float4*)&red[rbase + 8] = make_float4(cN[0], cN[1], cN[2], cN[3]);
        }
        __syncthreads();

        if (kh == 0) {
            float4 pR = *(const float4*)&red[rbase];
            float4 pZ = *(const float4*)&red[rbase + 4];
            float4 pN = *(const float4*)&red[rbase + 8];
            cR[0] += pR.x; cR[1] += pR.y; cR[2] += pR.z; cR[3] += pR.w;
            cZ[0] += pZ.x; cZ[1] += pZ.y; cZ[2] += pZ.z; cZ[3] += pZ.w;
            cN[0] += pN.x; cN[1] += pN.y; cN[2] += pN.z; cN[3] += pN.w;

            float2 fR0 = __half22float2(cur[0][0]), fR1 = __half22float2(cur[0][1]);
            float2 fZ0 = __half22float2(cur[1][0]), fZ1 = __half22float2(cur[1][1]);
            float2 fN0 = __half22float2(cur[2][0]), fN1 = __half22float2(cur[2][1]);
            float gR[4] = {fR0.x, fR0.y, fR1.x, fR1.y};
            float gZ[4] = {fZ0.x, fZ0.y, fZ1.x, fZ1.y};
            float gN[4] = {fN0.x, fN0.y, fN1.x, fN1.y};
            float bRl[4] = {bR.x, bR.y, bR.x, bR.y};
            float bZl[4] = {bZ.x, bZ.y, bZ.x, bZ.y};
            float bNl[4] = {bN.x, bN.y, bN.x, bN.y};

            float hn[4];
#pragma unroll
            for (int e = 0; e < 4; e++) {
                float rr = 1.0f / (1.0f + __expf(-(gR[e] + cR[e] + bRl[e])));
                float zz = 1.0f / (1.0f + __expf(-(gZ[e] + cZ[e] + bZl[e])));
                float y  = gN[e] + rr * (cN[e] + bNl[e]);
                float th = 1.0f - 2.0f / (__expf(2.0f * y) + 1.0f);
                hn[e] = th + zz * (hprev[e] - th);
                hprev[e] = hn[e];
            }

            __half2 hv0 = __floats2half2_rn(hn[0], hn[1]);
            __half2 hv1 = __floats2half2_rn(hn[2], hn[3]);
            unsigned hv0u = *(unsigned*)&hv0;
            unsigned hv1u = *(unsigned*)&hv1;

            *(unsigned*)&h16buf[((size_t)t * N_ + c0row + g) * H_ + jg]     = hv0u;
            *(unsigned*)&h16buf[((size_t)t * N_ + c0row + g + 8) * H_ + jg] = hv1u;
            if (t == L_ - 1) {
                *(float2*)&hn_out[(size_t)(c0row + g) * H_ + jg]     = make_float2(hn[0], hn[1]);
                *(float2*)&hn_out[(size_t)(c0row + g + 8) * H_ + jg] = make_float2(hn[2], hn[3]);
            }

            *(unsigned*)&h16[p ^ 1][g * 264 + jg]       = hv0u;
            *(unsigned*)&h16[p ^ 1][(g + 8) * 264 + jg] = hv1u;
            uint32_t o0 = h16_b + (((p ^ 1) * 16 * 264 + g * 264 + jg) << 1);
            uint32_t o1 = h16_b + (((p ^ 1) * 16 * 264 + (g + 8) * 264 + jg) << 1);
#pragma unroll
            for (int rr2 = 0; rr2 < 4; rr2++) {
                if ((uint32_t)rr2 != rk) {
                    st_cluster_u32(mapa_u32(o0, rr2), hv0u);
                    st_cluster_u32(mapa_u32(o1, rr2), hv1u);
                }
            }

#pragma unroll
            for (int gate = 0; gate < 3; gate++) {
                cur[gate][0] = nxt[gate][0];
                cur[gate][1] = nxt[gate][1];
            }
        }

        // ---- lightweight cluster step-sync via mbarriers ----
        __syncthreads();                 // all local stores/reads of this step done
        if (tid == 0) {
#pragma unroll
            for (int rr2 = 0; rr2 < 4; rr2++)
                mbar_arrive_cluster(mbar_b, (uint32_t)rr2);
        }
        mbar_wait_parity_cluster(mbar_b, (uint32_t)(t & 1));
    }

    CLUSTER_BAR();   // no CTA exits while peers' remote ops may target it
}

// ---------------- fused heads via HMMA (proven) ----------------
#define HD2_SMEM (2 * 128 * 264 * 2)
__global__ void __launch_bounds__(512, 1)
fused_heads_hmma(const __half* __restrict__ Hb,
                 const __half* __restrict__ Whd,
                 const float*  __restrict__ b_mu,
                 const float*  __restrict__ b_lv,
                 const float*  __restrict__ eps,
                 float* __restrict__ z_out,
                 float* __restrict__ mu_out,
                 float* __restrict__ lv_out)
{
    extern __shared__ __half hsm[];
    __half* Xs = hsm;
    __half* Ws = hsm + 128 * 264;
    float*  Cs = (float*)hsm;

    const int tid  = threadIdx.x;
    const int row0 = blockIdx.x * 128;

#pragma unroll
    for (int f = tid; f < 128 * 32; f += 512) {
        int m = f >> 5, c = f & 31;
        int4 v = *(const int4*)&Hb[((size_t)(row0 + m)) * H_ + c * 8];
        *(int4*)&Xs[m * 264 + c * 8] = v;
    }
#pragma unroll
    for (int f = tid; f < 128 * 32; f += 512) {
        int n = f >> 5, c = f & 31;
        int4 v = *(const int4*)&Whd[((size_t)n) * H_ + c * 8];
        *(int4*)&Ws[n * 264 + c * 8] = v;
    }
    __syncthreads();

    const int warp = tid >> 5, lane = tid & 31;
    const int wm = warp >> 2, wn = warp & 3;
    const int mb = wm * 32, nb = wn * 32;
    const int g = lane >> 2, tig = lane & 3;

    float acc[2][4][4];
#pragma unroll
    for (int mt = 0; mt < 2; mt++)
#pragma unroll
        for (int nt = 0; nt < 4; nt++)
#pragma unroll
            for (int e = 0; e < 4; e++) acc[mt][nt][e] = 0.0f;

#pragma unroll
    for (int kc = 0; kc < 16; kc++) {
        int k0 = kc * 16;
        unsigned a[2][4];
#pragma unroll
        for (int mt = 0; mt < 2; mt++) {
            int r = mb + mt * 16 + g;
            a[mt][0] = *(const unsigned*)&Xs[r * 264 + k0 + 2 * tig];
            a[mt][1] = *(const unsigned*)&Xs[(r + 8) * 264 + k0 + 2 * tig];
            a[mt][2] = *(const unsigned*)&Xs[r * 264 + k0 + 2 * tig + 8];
            a[mt][3] = *(const unsigned*)&Xs[(r + 8) * 264 + k0 + 2 * tig + 8];
        }
#pragma unroll
        for (int nt = 0; nt < 4; nt++) {
            int n = nb + nt * 8 + g;
            unsigned b0 = *(const unsigned*)&Ws[n * 264 + k0 + 2 * tig];
            unsigned b1 = *(const unsigned*)&Ws[n * 264 + k0 + 2 * tig + 8];
#pragma unroll
            for (int mt = 0; mt < 2; mt++)
                hmma16816(acc[mt][nt], a[mt][0], a[mt][1], a[mt][2], a[mt][3], b0, b1);
        }
    }
    __syncthreads();

#pragma unroll
    for (int mt = 0; mt < 2; mt++)
#pragma unroll
        for (int nt = 0; nt < 4; nt++) {
            int r = mb + mt * 16 + g;
            int cl = nb + nt * 8 + 2 * tig;
            *(float2*)&Cs[r * 132 + cl]       = make_float2(acc[mt][nt][0], acc[mt][nt][1]);
            *(float2*)&Cs[(r + 8) * 132 + cl] = make_float2(acc[mt][nt][2], acc[mt][nt][3]);
        }
    __syncthreads();

#pragma unroll
    for (int f = tid; f < 128 * 64; f += 512) {
        int lm = f >> 6, d = f & 63;
        float muv = Cs[lm * 132 + d]      + b_mu[d];
        float lvv = Cs[lm * 132 + 64 + d] + b_lv[d];
        size_t gi = ((size_t)(row0 + lm)) * 64 + d;
        float zv = muv + eps[gi] * expf(0.5f * lvv);
        z_out[gi]  = zv;
        mu_out[gi] = muv;
        lv_out[gi] = lvv;
    }
}

__global__ void noop_kernel() {}

extern "C" void kernel_launch(void* const* d_in, const int* in_sizes, int n_in,
                              void* d_out, int out_size)
{
    const float* x    = (const float*)d_in[0];
    const float* W_ih = (const float*)d_in[1];
    const float* b_ih = (const float*)d_in[2];
    const float* W_hh = (const float*)d_in[3];
    const float* b_hh = (const float*)d_in[4];
    const float* W_mu = (const float*)d_in[5];
    const float* b_mu = (const float*)d_in[6];
    const float* W_lv = (const float*)d_in[7];
    const float* b_lv = (const float*)d_in[8];
    const float* eps  = (const float*)d_in[9];

    float* out = (float*)d_out;
    float* z_out  = out;
    float* mu_out = out + (size_t)LN * DOUT_;
    float* lv_out = out + 2 * (size_t)LN * DOUT_;
    float* hn_out = out + 3 * (size_t)LN * DOUT_;

    __half *gx16, *whh16, *wih16, *whd16, *h16buf;
    cudaGetSymbolAddress((void**)&gx16,   g_gx16);
    cudaGetSymbolAddress((void**)&h16buf, g_h16);
    cudaGetSymbolAddress((void**)&whh16,  g_whh16);
    cudaGetSymbolAddress((void**)&wih16,  g_wih16);
    cudaGetSymbolAddress((void**)&whd16,  g_whd16);

    static bool attr_set = false;
    if (!attr_set) {
        cudaFuncSetAttribute(gemm_gx_hmma,     cudaFuncAttributeMaxDynamicSharedMemorySize, GXH_SMEM);
        cudaFuncSetAttribute(fused_heads_hmma, cudaFuncAttributeMaxDynamicSharedMemorySize, HD2_SMEM);
        attr_set = true;
    }

    // (1) padding launch (keeps the scan at capture slot #4)
    noop_kernel<<<1, 32>>>();

    // (2) weight conversions
    const int prep_n = G3 * H_ + G3 * DIN_ + 128 * H_;
    prep_weights<<<(prep_n + 255) / 256, 256>>>(W_hh, W_ih, W_mu, W_lv, whh16, wih16, whd16);

    // (3) gx = x @ W_ih^T + b_ih  (HMMA, fp32 in / fp16 out, conversion fused)
    {
        dim3 grid(G3 / 192, LN / 128);
        gemm_gx_hmma<<<grid, 512, GXH_SMEM>>>(x, wih16, b_ih, gx16);
    }

    // (4) cluster-cooperative HMMA GRU scan v5 (mbarrier step-sync)
    gru_scan_cluster<<<128, 512>>>(gx16, whh16, b_hh, h16buf, hn_out);

    // (5) fused heads + reparameterization via HMMA
    fused_heads_hmma<<<LN / 128, 512, HD2_SMEM>>>(h16buf, whd16, b_mu, b_lv, eps,
                                                  z_out, mu_out, lv_out);
}

// round 15
// speedup vs baseline: 1.1526x; 1.1526x over previous
#include <cuda_runtime.h>
#include <cuda_fp16.h>
#include <stdint.h>
#include <math.h>

#define L_    512
#define N_    512
#define DIN_  128
#define H_    256
#define DOUT_ 64
#define G3    768
#define LN    262144

typedef unsigned long long ull;

// ---- scratch ----
__device__ __half g_gx16[(size_t)LN * G3];      // input projections fp16
__device__ __half g_h16[(size_t)LN * H_];       // hidden states fp16 (heads input)
__device__ __half g_whh16[(size_t)G3 * H_];     // W_hh fp16 (768,256)
__device__ __half g_wih16[(size_t)G3 * DIN_];   // W_ih fp16 (768,128)
__device__ __half g_whd16[(size_t)128 * H_];    // [W_mu;W_lv] fp16 (128,256) n-major

// ---------------- helpers ----------------
__device__ __forceinline__ uint32_t smem_u32(const void* p) {
    uint32_t a;
    asm("{ .reg .u64 t; cvta.to.shared.u64 t, %1; cvt.u32.u64 %0, t; }" : "=r"(a) : "l"(p));
    return a;
}
__device__ __forceinline__ uint32_t mapa_u32(uint32_t addr, uint32_t rank) {
    uint32_t r;
    asm volatile("mapa.shared::cluster.u32 %0, %1, %2;" : "=r"(r) : "r"(addr), "r"(rank));
    return r;
}
__device__ __forceinline__ void st_cluster_u32(uint32_t addr, unsigned v) {
    asm volatile("st.shared::cluster.u32 [%0], %1;" :: "r"(addr), "r"(v) : "memory");
}
__device__ __forceinline__ uint32_t my_rank() {
    uint32_t r;
    asm("mov.u32 %0, %%cluster_ctarank;" : "=r"(r));
    return r;
}
#define CLUSTER_BAR() do {                                        \
    asm volatile("barrier.cluster.arrive.aligned;" ::: "memory"); \
    asm volatile("barrier.cluster.wait.aligned;" ::: "memory");   \
} while (0)

__device__ __forceinline__ void hmma16816(float* c, unsigned a0, unsigned a1,
                                          unsigned a2, unsigned a3,
                                          unsigned b0, unsigned b1) {
    asm volatile(
        "mma.sync.aligned.m16n8k16.row.col.f32.f16.f16.f32 "
        "{%0,%1,%2,%3}, {%4,%5,%6,%7}, {%8,%9}, {%0,%1,%2,%3};"
        : "+f"(c[0]), "+f"(c[1]), "+f"(c[2]), "+f"(c[3])
        : "r"(a0), "r"(a1), "r"(a2), "r"(a3), "r"(b0), "r"(b1));
}

// ---------------- weight prep ----------------
__global__ void prep_weights(const float* __restrict__ Whh, const float* __restrict__ Wih,
                             const float* __restrict__ Wmu, const float* __restrict__ Wlv,
                             __half* __restrict__ whh16, __half* __restrict__ wih16,
                             __half* __restrict__ whd16)
{
    int i = blockIdx.x * blockDim.x + threadIdx.x;
    if (i < G3 * H_) {
        whh16[i] = __float2half_rn(Whh[i]);
    } else if (i < G3 * H_ + G3 * DIN_) {
        int j = i - G3 * H_;
        wih16[j] = __float2half_rn(Wih[j]);
    } else if (i < G3 * H_ + G3 * DIN_ + 128 * H_) {
        int j = i - G3 * H_ - G3 * DIN_;
        int d = j / H_;
        whd16[j] = __float2half_rn((d < 64) ? Wmu[j] : Wlv[j - 64 * H_]);
    }
}

// ---------------- gx GEMM via HMMA: fp32 x in (converted in staging), fp16 out ----------------
#define GXH_SMEM ((128 * 136 + 192 * 136) * 2)
__global__ void __launch_bounds__(512, 1)
gemm_gx_hmma(const float*  __restrict__ X,      // (LN,128) fp32
             const __half* __restrict__ W16,    // (768,128) fp16 n-major
             const float*  __restrict__ bias,   // (768)
             __half*       __restrict__ C16)    // (LN,768) fp16
{
    extern __shared__ __half hsm[];
    __half* Xs = hsm;              // [128][136]
    __half* Ws = hsm + 128 * 136;  // [192][136]

    const int tid = threadIdx.x;
    const int m0  = blockIdx.y * 128;
    const int n0  = blockIdx.x * 192;

    // stage x: fp32 -> fp16 in-flight
#pragma unroll
    for (int f = tid; f < 128 * 32; f += 512) {
        int m = f >> 5, c = f & 31;
        float4 v = *(const float4*)&X[((size_t)(m0 + m)) * DIN_ + 4 * c];
        __half2 h0 = __floats2half2_rn(v.x, v.y);
        __half2 h1 = __floats2half2_rn(v.z, v.w);
        *(__half2*)&Xs[m * 136 + 4 * c]     = h0;
        *(__half2*)&Xs[m * 136 + 4 * c + 2] = h1;
    }
#pragma unroll
    for (int f = tid; f < 192 * 16; f += 512) {
        int n = f >> 4, c = f & 15;
        int4 v = *(const int4*)&W16[((size_t)(n0 + n)) * DIN_ + c * 8];
        *(int4*)&Ws[n * 136 + c * 8] = v;
    }
    __syncthreads();

    const int warp = tid >> 5, lane = tid & 31;
    const int wm = warp >> 2, wn = warp & 3;
    const int mb = wm * 32, nb = wn * 48;
    const int g = lane >> 2, tig = lane & 3;

    float acc[2][6][4];
#pragma unroll
    for (int mt = 0; mt < 2; mt++)
#pragma unroll
        for (int nt = 0; nt < 6; nt++)
#pragma unroll
            for (int q = 0; q < 4; q++) acc[mt][nt][q] = 0.0f;

#pragma unroll
    for (int kc = 0; kc < 8; kc++) {
        int k0 = kc * 16;
        unsigned a[2][4];
#pragma unroll
        for (int mt = 0; mt < 2; mt++) {
            int r = mb + mt * 16 + g;
            a[mt][0] = *(const unsigned*)&Xs[r * 136 + k0 + 2 * tig];
            a[mt][1] = *(const unsigned*)&Xs[(r + 8) * 136 + k0 + 2 * tig];
            a[mt][2] = *(const unsigned*)&Xs[r * 136 + k0 + 2 * tig + 8];
            a[mt][3] = *(const unsigned*)&Xs[(r + 8) * 136 + k0 + 2 * tig + 8];
        }
#pragma unroll
        for (int nt = 0; nt < 6; nt++) {
            int n = nb + nt * 8 + g;
            unsigned b0 = *(const unsigned*)&Ws[n * 136 + k0 + 2 * tig];
            unsigned b1 = *(const unsigned*)&Ws[n * 136 + k0 + 2 * tig + 8];
#pragma unroll
            for (int mt = 0; mt < 2; mt++)
                hmma16816(acc[mt][nt], a[mt][0], a[mt][1], a[mt][2], a[mt][3], b0, b1);
        }
    }

#pragma unroll
    for (int nt = 0; nt < 6; nt++) {
        int col = n0 + nb + nt * 8 + 2 * tig;
        float b0 = __ldg(&bias[col]);
        float b1 = __ldg(&bias[col + 1]);
#pragma unroll
        for (int mt = 0; mt < 2; mt++) {
            size_t row = (size_t)m0 + mb + mt * 16 + g;
            __half2 o0 = __floats2half2_rn(acc[mt][nt][0] + b0, acc[mt][nt][1] + b1);
            __half2 o1 = __floats2half2_rn(acc[mt][nt][2] + b0, acc[mt][nt][3] + b1);
            *(__half2*)&C16[row * G3 + col]       = o0;
            *(__half2*)&C16[(row + 8) * G3 + col] = o1;
        }
    }
}

// ---------------- cluster-cooperative HMMA GRU scan, v6 ----------------
// = v4 (best): 16 warps, 2-way K-split, gate-owner warps kh=0, ONE hardware
// cluster barrier per step. Only change vs v4: gx is fp16 (half the read BW).
__global__ void __launch_bounds__(512, 1) __cluster_dims__(4, 1, 1)
gru_scan_cluster(const __half* __restrict__ gx,      // (L,N,768) fp16
                 const __half* __restrict__ W16,     // (768,256) fp16
                 const float*  __restrict__ b_hh,    // (768)
                 __half*       __restrict__ h16buf,  // (L,N,256) fp16
                 float*        __restrict__ hn_out)  // (N,256) fp32
{
    __shared__ __half h16[2][16 * 264];        // double-buffered fp16 h tile
    __shared__ float  red[8 * 32 * 12];        // K-split partials

    const int tid  = threadIdx.x;
    const int wid  = tid >> 5;
    const int kh   = wid >> 3;                 // K-half
    const int ug   = wid & 7;                  // unit group
    const int lane = tid & 31;
    const int g    = lane >> 2, tig = lane & 3;
    const uint32_t rk = my_rank();
    const int c0row = (blockIdx.x >> 2) * 16;
    const uint32_t h16_b = smem_u32(&h16[0][0]);

    // zero both h buffers (h0 = 0)
    for (int i = tid; i < 2 * 16 * 264 / 2; i += 512) ((unsigned*)&h16[0][0])[i] = 0u;

    const int j0 = ug * 8 + 2 * tig;
    const int jg = (int)rk * 64 + j0;

    unsigned bfr[3][8][2];
#pragma unroll
    for (int gate = 0; gate < 3; gate++) {
        int n = gate * 256 + (int)rk * 64 + ug * 8 + g;
        const __half* wp = W16 + (size_t)n * H_ + 2 * tig;
#pragma unroll
        for (int ks = 0; ks < 8; ks++) {
            int kso = kh * 8 + ks;
            bfr[gate][ks][0] = *(const unsigned*)(wp + kso * 16);
            bfr[gate][ks][1] = *(const unsigned*)(wp + kso * 16 + 8);
        }
    }

    const float2 bR = *(const float2*)&b_hh[jg];
    const float2 bZ = *(const float2*)&b_hh[H_ + jg];
    const float2 bN = *(const float2*)&b_hh[2 * H_ + jg];
    float hprev[4] = {0.f, 0.f, 0.f, 0.f};

    __half2 cur[3][2], nxt[3][2];
    if (kh == 0) {
        const __half* p0 = gx + ((size_t)c0row + g) * G3 + jg;
        const __half* p1 = gx + ((size_t)c0row + g + 8) * G3 + jg;
#pragma unroll
        for (int gate = 0; gate < 3; gate++) {
            cur[gate][0] = *(const __half2*)(p0 + gate * H_);
            cur[gate][1] = *(const __half2*)(p1 + gate * H_);
        }
    }

    const int rbase = (ug * 32 + lane) * 12;

    CLUSTER_BAR();

    for (int t = 0; t < L_; t++) {
        const int p = t & 1;
        const __half* hp = &h16[p][0];

        // prefetch gx(t+1) first (drains under MMA + gate)
        if (kh == 0 && t + 1 < L_) {
            const __half* p0 = gx + ((size_t)(t + 1) * N_ + c0row + g) * G3 + jg;
            const __half* p1 = gx + ((size_t)(t + 1) * N_ + c0row + g + 8) * G3 + jg;
#pragma unroll
            for (int gate = 0; gate < 3; gate++) {
                nxt[gate][0] = *(const __half2*)(p0 + gate * H_);
                nxt[gate][1] = *(const __half2*)(p1 + gate * H_);
            }
        }

        // MMA: 3 gates x 8 ksteps (this warp's K-half)
        float cR[4] = {0.f, 0.f, 0.f, 0.f};
        float cZ[4] = {0.f, 0.f, 0.f, 0.f};
        float cN[4] = {0.f, 0.f, 0.f, 0.f};
#pragma unroll
        for (int ks = 0; ks < 8; ks++) {
            int ko = (kh * 8 + ks) * 16 + 2 * tig;
            unsigned a0 = *(const unsigned*)&hp[g * 264 + ko];
            unsigned a1 = *(const unsigned*)&hp[(g + 8) * 264 + ko];
            unsigned a2 = *(const unsigned*)&hp[g * 264 + ko + 8];
            unsigned a3 = *(const unsigned*)&hp[(g + 8) * 264 + ko + 8];
            hmma16816(cR, a0, a1, a2, a3, bfr[0][ks][0], bfr[0][ks][1]);
            hmma16816(cZ, a0, a1, a2, a3, bfr[1][ks][0], bfr[1][ks][1]);
            hmma16816(cN, a0, a1, a2, a3, bfr[2][ks][0], bfr[2][ks][1]);
        }

        if (kh == 1) {
            *(float4*)&red[rbase]     = make_float4(cR[0], cR[1], cR[2], cR[3]);
            *(float4*)&red[rbase + 4] = make_float4(cZ[0], cZ[1], cZ[2], cZ[3]);
            *(float4*)&red[rbase + 8] = make_float4(cN[0], cN[1], cN[2], cN[3]);
        }
        __syncthreads();

        if (kh == 0) {
            float4 pR = *(const float4*)&red[rbase];
            float4 pZ = *(const float4*)&red[rbase + 4];
            float4 pN = *(const float4*)&red[rbase + 8];
            cR[0] += pR.x; cR[1] += pR.y; cR[2] += pR.z; cR[3] += pR.w;
            cZ[0] += pZ.x; cZ[1] += pZ.y; cZ[2] += pZ.z; cZ[3] += pZ.w;
            cN[0] += pN.x; cN[1] += pN.y; cN[2] += pN.z; cN[3] += pN.w;

            float2 fR0 = __half22float2(cur[0][0]), fR1 = __half22float2(cur[0][1]);
            float2 fZ0 = __half22float2(cur[1][0]), fZ1 = __half22float2(cur[1][1]);
            float2 fN0 = __half22float2(cur[2][0]), fN1 = __half22float2(cur[2][1]);
            float gR[4] = {fR0.x, fR0.y, fR1.x, fR1.y};
            float gZ[4] = {fZ0.x, fZ0.y, fZ1.x, fZ1.y};
            float gN[4] = {fN0.x, fN0.y, fN1.x, fN1.y};
            float bRl[4] = {bR.x, bR.y, bR.x, bR.y};
            float bZl[4] = {bZ.x, bZ.y, bZ.x, bZ.y};
            float bNl[4] = {bN.x, bN.y, bN.x, bN.y};

            float hn[4];
#pragma unroll
            for (int e = 0; e < 4; e++) {
                float rr = 1.0f / (1.0f + __expf(-(gR[e] + cR[e] + bRl[e])));
                float zz = 1.0f / (1.0f + __expf(-(gZ[e] + cZ[e] + bZl[e])));
                float y  = gN[e] + rr * (cN[e] + bNl[e]);
                float th = 1.0f - 2.0f / (__expf(2.0f * y) + 1.0f);
                hn[e] = th + zz * (hprev[e] - th);
                hprev[e] = hn[e];
            }

            __half2 hv0 = __floats2half2_rn(hn[0], hn[1]);
            __half2 hv1 = __floats2half2_rn(hn[2], hn[3]);
            unsigned hv0u = *(unsigned*)&hv0;
            unsigned hv1u = *(unsigned*)&hv1;

            *(unsigned*)&h16buf[((size_t)t * N_ + c0row + g) * H_ + jg]     = hv0u;
            *(unsigned*)&h16buf[((size_t)t * N_ + c0row + g + 8) * H_ + jg] = hv1u;
            if (t == L_ - 1) {
                *(float2*)&hn_out[(size_t)(c0row + g) * H_ + jg]     = make_float2(hn[0], hn[1]);
                *(float2*)&hn_out[(size_t)(c0row + g + 8) * H_ + jg] = make_float2(hn[2], hn[3]);
            }

            *(unsigned*)&h16[p ^ 1][g * 264 + jg]       = hv0u;
            *(unsigned*)&h16[p ^ 1][(g + 8) * 264 + jg] = hv1u;
            uint32_t o0 = h16_b + (((p ^ 1) * 16 * 264 + g * 264 + jg) << 1);
            uint32_t o1 = h16_b + (((p ^ 1) * 16 * 264 + (g + 8) * 264 + jg) << 1);
#pragma unroll
            for (int rr2 = 0; rr2 < 4; rr2++) {
                if ((uint32_t)rr2 != rk) {
                    st_cluster_u32(mapa_u32(o0, rr2), hv0u);
                    st_cluster_u32(mapa_u32(o1, rr2), hv1u);
                }
            }

#pragma unroll
            for (int gate = 0; gate < 3; gate++) {
                cur[gate][0] = nxt[gate][0];
                cur[gate][1] = nxt[gate][1];
            }
        }

        CLUSTER_BAR();   // broadcasts visible everywhere; h16[p] reads done
    }
}

// ---------------- fused heads via HMMA (proven) ----------------
#define HD2_SMEM (2 * 128 * 264 * 2)
__global__ void __launch_bounds__(512, 1)
fused_heads_hmma(const __half* __restrict__ Hb,
                 const __half* __restrict__ Whd,
                 const float*  __restrict__ b_mu,
                 const float*  __restrict__ b_lv,
                 const float*  __restrict__ eps,
                 float* __restrict__ z_out,
                 float* __restrict__ mu_out,
                 float* __restrict__ lv_out)
{
    extern __shared__ __half hsm[];
    __half* Xs = hsm;
    __half* Ws = hsm + 128 * 264;
    float*  Cs = (float*)hsm;

    const int tid  = threadIdx.x;
    const int row0 = blockIdx.x * 128;

#pragma unroll
    for (int f = tid; f < 128 * 32; f += 512) {
        int m = f >> 5, c = f & 31;
        int4 v = *(const int4*)&Hb[((size_t)(row0 + m)) * H_ + c * 8];
        *(int4*)&Xs[m * 264 + c * 8] = v;
    }
#pragma unroll
    for (int f = tid; f < 128 * 32; f += 512) {
        int n = f >> 5, c = f & 31;
        int4 v = *(const int4*)&Whd[((size_t)n) * H_ + c * 8];
        *(int4*)&Ws[n * 264 + c * 8] = v;
    }
    __syncthreads();

    const int warp = tid >> 5, lane = tid & 31;
    const int wm = warp >> 2, wn = warp & 3;
    const int mb = wm * 32, nb = wn * 32;
    const int g = lane >> 2, tig = lane & 3;

    float acc[2][4][4];
#pragma unroll
    for (int mt = 0; mt < 2; mt++)
#pragma unroll
        for (int nt = 0; nt < 4; nt++)
#pragma unroll
            for (int e = 0; e < 4; e++) acc[mt][nt][e] = 0.0f;

#pragma unroll
    for (int kc = 0; kc < 16; kc++) {
        int k0 = kc * 16;
        unsigned a[2][4];
#pragma unroll
        for (int mt = 0; mt < 2; mt++) {
            int r = mb + mt * 16 + g;
            a[mt][0] = *(const unsigned*)&Xs[r * 264 + k0 + 2 * tig];
            a[mt][1] = *(const unsigned*)&Xs[(r + 8) * 264 + k0 + 2 * tig];
            a[mt][2] = *(const unsigned*)&Xs[r * 264 + k0 + 2 * tig + 8];
            a[mt][3] = *(const unsigned*)&Xs[(r + 8) * 264 + k0 + 2 * tig + 8];
        }
#pragma unroll
        for (int nt = 0; nt < 4; nt++) {
            int n = nb + nt * 8 + g;
            unsigned b0 = *(const unsigned*)&Ws[n * 264 + k0 + 2 * tig];
            unsigned b1 = *(const unsigned*)&Ws[n * 264 + k0 + 2 * tig + 8];
#pragma unroll
            for (int mt = 0; mt < 2; mt++)
                hmma16816(acc[mt][nt], a[mt][0], a[mt][1], a[mt][2], a[mt][3], b0, b1);
        }
    }
    __syncthreads();

#pragma unroll
    for (int mt = 0; mt < 2; mt++)
#pragma unroll
        for (int nt = 0; nt < 4; nt++) {
            int r = mb + mt * 16 + g;
            int cl = nb + nt * 8 + 2 * tig;
            *(float2*)&Cs[r * 132 + cl]       = make_float2(acc[mt][nt][0], acc[mt][nt][1]);
            *(float2*)&Cs[(r + 8) * 132 + cl] = make_float2(acc[mt][nt][2], acc[mt][nt][3]);
        }
    __syncthreads();

#pragma unroll
    for (int f = tid; f < 128 * 64; f += 512) {
        int lm = f >> 6, d = f & 63;
        float muv = Cs[lm * 132 + d]      + b_mu[d];
        float lvv = Cs[lm * 132 + 64 + d] + b_lv[d];
        size_t gi = ((size_t)(row0 + lm)) * 64 + d;
        float zv = muv + eps[gi] * expf(0.5f * lvv);
        z_out[gi]  = zv;
        mu_out[gi] = muv;
        lv_out[gi] = lvv;
    }
}

__global__ void noop_kernel() {}

extern "C" void kernel_launch(void* const* d_in, const int* in_sizes, int n_in,
                              void* d_out, int out_size)
{
    const float* x    = (const float*)d_in[0];
    const float* W_ih = (const float*)d_in[1];
    const float* b_ih = (const float*)d_in[2];
    const float* W_hh = (const float*)d_in[3];
    const float* b_hh = (const float*)d_in[4];
    const float* W_mu = (const float*)d_in[5];
    const float* b_mu = (const float*)d_in[6];
    const float* W_lv = (const float*)d_in[7];
    const float* b_lv = (const float*)d_in[8];
    const float* eps  = (const float*)d_in[9];

    float* out = (float*)d_out;
    float* z_out  = out;
    float* mu_out = out + (size_t)LN * DOUT_;
    float* lv_out = out + 2 * (size_t)LN * DOUT_;
    float* hn_out = out + 3 * (size_t)LN * DOUT_;

    __half *gx16, *whh16, *wih16, *whd16, *h16buf;
    cudaGetSymbolAddress((void**)&gx16,   g_gx16);
    cudaGetSymbolAddress((void**)&h16buf, g_h16);
    cudaGetSymbolAddress((void**)&whh16,  g_whh16);
    cudaGetSymbolAddress((void**)&wih16,  g_wih16);
    cudaGetSymbolAddress((void**)&whd16,  g_whd16);

    static bool attr_set = false;
    if (!attr_set) {
        cudaFuncSetAttribute(gemm_gx_hmma,     cudaFuncAttributeMaxDynamicSharedMemorySize, GXH_SMEM);
        cudaFuncSetAttribute(fused_heads_hmma, cudaFuncAttributeMaxDynamicSharedMemorySize, HD2_SMEM);
        attr_set = true;
    }

    // (1) padding launch (keeps the scan at capture slot #4)
    noop_kernel<<<1, 32>>>();

    // (2) weight conversions
    const int prep_n = G3 * H_ + G3 * DIN_ + 128 * H_;
    prep_weights<<<(prep_n + 255) / 256, 256>>>(W_hh, W_ih, W_mu, W_lv, whh16, wih16, whd16);

    // (3) gx = x @ W_ih^T + b_ih  (HMMA, fp32 in / fp16 out, conversion fused)
    {
        dim3 grid(G3 / 192, LN / 128);
        gemm_gx_hmma<<<grid, 512, GXH_SMEM>>>(x, wih16, b_ih, gx16);
    }

    // (4) cluster-cooperative HMMA GRU scan v6 = v4 + fp16 gx (HW cluster barrier)
    gru_scan_cluster<<<128, 512>>>(gx16, whh16, b_hh, h16buf, hn_out);

    // (5) fused heads + reparameterization via HMMA
    fused_heads_hmma<<<LN / 128, 512, HD2_SMEM>>>(h16buf, whd16, b_mu, b_lv, eps,
                                                  z_out, mu_out, lv_out);
}